// round 3
// baseline (speedup 1.0000x reference)
#include <cuda_runtime.h>
#include <math.h>

#define BB   16
#define NN   16000
#define GG   128
#define NPG  (NN + GG)          /* 16128 = 63 * 256 exactly */
#define IMGW 800.0f
#define IMGH 800.0f
#define XCLIP 4.135166556742356f   /* log(1000/16) */

#define NBX   10                /* 10x10 bins of 80px; boxes <=64px span <=2x2 */
#define NBINS (NBX * NBX)
#define BINW_INV (1.0f / 80.0f)
#define CAP   128

#define GRID_X (NPG / 256)      /* 63 */
#define NBLOCKS (GRID_X * BB)   /* 1008 */

// Cross-block scratch: per-GT argmax keys (q_bits<<32)|(0xFFFFFFFF-idx).
// Zero-initialized at module load = valid "no hit" state (q==0).
// Consumed-and-reset atomically by the last block each call.
__device__ unsigned long long g_keys[BB * GG];
__device__ unsigned int       g_ticket;

__device__ __forceinline__ float4 ld4(const float* p) {
    return *reinterpret_cast<const float4*>(p);
}

__global__ __launch_bounds__(256)
void fused_kernel(const float* __restrict__ props,
                  const float* __restrict__ gts,
                  const float* __restrict__ reg,
                  float* __restrict__ out_pred,
                  float* __restrict__ out_labels,
                  float* __restrict__ out_regt,
                  float* __restrict__ out_scores) {
    __shared__ float4        sg[GG];
    __shared__ float         sa[GG];
    __shared__ int           scnt[NBINS];
    __shared__ unsigned char sent[NBINS * CAP];
    __shared__ unsigned int  s_last;

    const int b   = blockIdx.y;
    const int tid = threadIdx.x;
    const float* gt_b = gts + (size_t)b * GG * 4;

    if (tid < NBINS) scnt[tid] = 0;
    __syncthreads();

    // ---- bin the 128 GT boxes (each spans <=2x2 bins) ----
    if (tid < GG) {
        float4 v = ld4(gt_b + tid * 4);
        sg[tid] = v;
        sa[tid] = __fmul_rn(__fsub_rn(v.z, v.x), __fsub_rn(v.w, v.y));
        int bx0 = (int)(v.x * BINW_INV);
        int bx1 = (int)(v.z * BINW_INV); if (bx1 > NBX - 1) bx1 = NBX - 1;
        int by0 = (int)(v.y * BINW_INV);
        int by1 = (int)(v.w * BINW_INV); if (by1 > NBX - 1) by1 = NBX - 1;
        for (int by = by0; by <= by1; by++)
            for (int bx = bx0; bx <= bx1; bx++) {
                int bin = by * NBX + bx;
                int pos = atomicAdd(&scnt[bin], 1);
                sent[bin * CAP + pos] = (unsigned char)tid;
            }
    }
    __syncthreads();

    const int p = blockIdx.x * 256 + tid;   // always < NPG (grid sized exactly)

    float4 a = (p < NN) ? ld4(props + ((size_t)b * NN + p) * 4) : sg[p - NN];

    // ---- decode + clip (pred_boxes) ----
    {
        float4 r = ld4(reg + ((size_t)b * NPG + p) * 4);
        float pw  = __fsub_rn(a.z, a.x);
        float ph  = __fsub_rn(a.w, a.y);
        float pcx = __fadd_rn(a.x, __fmul_rn(0.5f, pw));
        float pcy = __fadd_rn(a.y, __fmul_rn(0.5f, ph));
        float dx = __fdiv_rn(r.x, 10.0f);
        float dy = __fdiv_rn(r.y, 10.0f);
        float dw = fminf(__fdiv_rn(r.z, 5.0f), XCLIP);
        float dh = fminf(__fdiv_rn(r.w, 5.0f), XCLIP);
        float ncx = __fadd_rn(__fmul_rn(dx, pw), pcx);
        float ncy = __fadd_rn(__fmul_rn(dy, ph), pcy);
        float nw  = __fmul_rn(expf(dw), pw);
        float nh  = __fmul_rn(expf(dh), ph);
        float4 o;
        o.x = fminf(fmaxf(__fsub_rn(ncx, __fmul_rn(0.5f, nw)), 0.0f), IMGW);
        o.y = fminf(fmaxf(__fsub_rn(ncy, __fmul_rn(0.5f, nh)), 0.0f), IMGH);
        o.z = fminf(fmaxf(__fadd_rn(ncx, __fmul_rn(0.5f, nw)), 0.0f), IMGW);
        o.w = fminf(fmaxf(__fadd_rn(ncy, __fmul_rn(0.5f, nh)), 0.0f), IMGH);
        *reinterpret_cast<float4*>(out_pred + ((size_t)b * NPG + p) * 4) = o;
    }

    // ---- IoU over binned GT candidates; atomicMax on hits ----
    {
        const float area_a = __fmul_rn(__fsub_rn(a.z, a.x), __fsub_rn(a.w, a.y));
        float vmax = 0.0f;
        unsigned long long* keyrow = g_keys + b * GG;
        const unsigned low = 0xFFFFFFFFu - (unsigned)p;
        const bool isprop = (p < NN);

        int bx0 = (int)(a.x * BINW_INV);
        int bx1 = (int)(a.z * BINW_INV); if (bx1 > NBX - 1) bx1 = NBX - 1;
        int by0 = (int)(a.y * BINW_INV);
        int by1 = (int)(a.w * BINW_INV); if (by1 > NBX - 1) by1 = NBX - 1;

        for (int by = by0; by <= by1; by++)
            for (int bx = bx0; bx <= bx1; bx++) {
                int bin = by * NBX + bx;
                int cnt = scnt[bin];
                const unsigned char* ent = sent + bin * CAP;
                for (int k = 0; k < cnt; k++) {
                    int g = ent[k];
                    float4 gb = sg[g];
                    float ltx = fmaxf(a.x, gb.x);
                    float lty = fmaxf(a.y, gb.y);
                    float rbx = fminf(a.z, gb.z);
                    float rby = fminf(a.w, gb.w);
                    float w = __fsub_rn(rbx, ltx);
                    float h = __fsub_rn(rby, lty);
                    if (w > 0.0f && h > 0.0f) {
                        float inter = __fmul_rn(w, h);
                        float uni   = __fsub_rn(__fadd_rn(sa[g], area_a), inter);
                        float q     = __fdiv_rn(inter, uni);
                        vmax = fmaxf(vmax, q);
                        if (isprop) {
                            unsigned long long key =
                                ((unsigned long long)__float_as_uint(q) << 32) | low;
                            atomicMax(keyrow + g, key);
                        }
                    }
                }
            }

        out_labels[(size_t)b * NPG + p] = (vmax >= 0.5f) ? 1.0f : 0.0f;
    }

    // ---- fence-and-ticket: last block runs the encode epilogue ----
    __threadfence();
    __syncthreads();
    if (tid == 0) {
        unsigned t = atomicAdd(&g_ticket, 1u);
        s_last = (t == NBLOCKS - 1) ? 1u : 0u;
    }
    __syncthreads();
    if (!s_last) return;

    if (tid == 0) g_ticket = 0;   // reset for next call

#pragma unroll
    for (int k = 0; k < (BB * GG) / 256; k++) {
        int i  = k * 256 + tid;
        int bb = i >> 7;            // /GG
        int g  = i & (GG - 1);

        // atomic read + reset-to-zero for next call (L2-coherent)
        unsigned long long key = atomicExch(&g_keys[i], 0ull);
        float q = __uint_as_float((unsigned)(key >> 32));
        unsigned idx = (key == 0ull) ? 0u
                     : (0xFFFFFFFFu - (unsigned)(key & 0xFFFFFFFFull));

        float4 mp = ld4(props + ((size_t)bb * NN + idx) * 4);
        float4 gb = ld4(gts + ((size_t)bb * GG + g) * 4);

        float pw  = __fsub_rn(mp.z, mp.x);
        float ph  = __fsub_rn(mp.w, mp.y);
        float pcx = __fadd_rn(mp.x, __fmul_rn(0.5f, pw));
        float pcy = __fadd_rn(mp.y, __fmul_rn(0.5f, ph));
        float gw  = __fsub_rn(gb.z, gb.x);
        float gh  = __fsub_rn(gb.w, gb.y);
        float gcx = __fadd_rn(gb.x, __fmul_rn(0.5f, gw));
        float gcy = __fadd_rn(gb.y, __fmul_rn(0.5f, gh));

        float dx = __fdiv_rn(__fmul_rn(10.0f, __fsub_rn(gcx, pcx)), pw);
        float dy = __fdiv_rn(__fmul_rn(10.0f, __fsub_rn(gcy, pcy)), ph);
        float dw = __fmul_rn(5.0f, logf(__fdiv_rn(gw, pw)));
        float dh = __fmul_rn(5.0f, logf(__fdiv_rn(gh, ph)));

        float* o = out_regt + (size_t)i * 4;
        o[0] = dx; o[1] = dy; o[2] = dw; o[3] = dh;
        out_scores[i] = q;
    }
}

// ---------------------------------------------------------------------------
extern "C" void kernel_launch(void* const* d_in, const int* in_sizes, int n_in,
                              void* d_out, int out_size) {
    const float* props = (const float*)d_in[0];   // (B, N, 4)
    const float* gts   = (const float*)d_in[1];   // (B, G, 4)
    const float* reg   = (const float*)d_in[2];   // (B, N+G, 4)

    float* out        = (float*)d_out;
    float* out_pred   = out;                                  // B*(N+G)*4
    float* out_regt   = out_pred + (size_t)BB * NPG * 4;      // B*G*4
    float* out_scores = out_regt + (size_t)BB * GG * 4;       // B*G
    float* out_labels = out_scores + (size_t)BB * GG;         // B*(N+G)

    dim3 gm(GRID_X, BB);
    fused_kernel<<<gm, 256>>>(props, gts, reg,
                              out_pred, out_labels, out_regt, out_scores);
}

// round 4
// speedup vs baseline: 1.6697x; 1.6697x over previous
#include <cuda_runtime.h>
#include <math.h>

#define BB   16
#define NN   16000
#define GG   128
#define NPG  (NN + GG)          /* 16128 = 63 * 256 exactly */
#define IMGW 800.0f
#define IMGH 800.0f
#define XCLIP 4.135166556742356f   /* log(1000/16) */
#define MAXWH 64.0f             /* boxes are at most 64px wide/tall */

#define NBX   12
#define NBINS (NBX * NBX)
#define BINW_INV (12.0f / 800.0f)

#define GRID_X (NPG / 256)      /* 63 */

// Per-GT argmax keys: (q_bits<<32) | (0xFFFFFFFF - idx).
// Zero at module load == valid "no hit" state; epilogue resets to zero
// via atomicExch so every graph replay starts clean.
__device__ unsigned long long g_keys[BB * GG];

__device__ __forceinline__ float4 ld4(const float* p) {
    return *reinterpret_cast<const float4*>(p);
}

// ---------------------------------------------------------------------------
// Main kernel: decode+clip, labels, per-GT argmax (atomicMax on hits).
// GT candidates via per-bin 128-bit masks; proposals probe ONE bin (their
// top-left corner bin); GTs are registered dilated 64px left/up so the
// single-bin probe is a superset of all intersecting pairs.
// ---------------------------------------------------------------------------
__global__ __launch_bounds__(256)
void main_kernel(const float* __restrict__ props,
                 const float* __restrict__ gts,
                 const float* __restrict__ reg,
                 float* __restrict__ out_pred,
                 float* __restrict__ out_labels) {
    __shared__ float4       sg[GG];
    __shared__ float        sa[GG];
    __shared__ unsigned int smask[NBINS * 4];

    const int b   = blockIdx.y;
    const int tid = threadIdx.x;
    const float* gt_b = gts + (size_t)b * GG * 4;

    // zero masks (576 words / 256 threads)
    for (int i = tid; i < NBINS * 4; i += 256) smask[i] = 0u;
    __syncthreads();

    // ---- register GT boxes into corner-bin masks (dilated 64px left/up) ----
    if (tid < GG) {
        float4 v = ld4(gt_b + tid * 4);
        sg[tid] = v;
        sa[tid] = __fmul_rn(__fsub_rn(v.z, v.x), __fsub_rn(v.w, v.y));
        int bx0 = (int)(fmaxf(v.x - MAXWH, 0.0f) * BINW_INV);
        int bx1 = (int)(v.z * BINW_INV); if (bx1 > NBX - 1) bx1 = NBX - 1;
        int by0 = (int)(fmaxf(v.y - MAXWH, 0.0f) * BINW_INV);
        int by1 = (int)(v.w * BINW_INV); if (by1 > NBX - 1) by1 = NBX - 1;
        const unsigned bit  = 1u << (tid & 31);
        const int      word = tid >> 5;
        for (int by = by0; by <= by1; by++)
            for (int bx = bx0; bx <= bx1; bx++)
                atomicOr(&smask[(by * NBX + bx) * 4 + word], bit);
    }
    __syncthreads();

    const int p = blockIdx.x * 256 + tid;   // grid sized exactly, p < NPG
    const bool isprop = (p < NN);

    float4 a = isprop ? ld4(props + ((size_t)b * NN + p) * 4) : sg[p - NN];

    // ---- decode + clip (pred_boxes) ----
    {
        float4 r = ld4(reg + ((size_t)b * NPG + p) * 4);
        float pw  = __fsub_rn(a.z, a.x);
        float ph  = __fsub_rn(a.w, a.y);
        float pcx = __fadd_rn(a.x, __fmul_rn(0.5f, pw));
        float pcy = __fadd_rn(a.y, __fmul_rn(0.5f, ph));
        float dx = __fdiv_rn(r.x, 10.0f);
        float dy = __fdiv_rn(r.y, 10.0f);
        float dw = fminf(__fdiv_rn(r.z, 5.0f), XCLIP);
        float dh = fminf(__fdiv_rn(r.w, 5.0f), XCLIP);
        float ncx = __fadd_rn(__fmul_rn(dx, pw), pcx);
        float ncy = __fadd_rn(__fmul_rn(dy, ph), pcy);
        float nw  = __fmul_rn(expf(dw), pw);
        float nh  = __fmul_rn(expf(dh), ph);
        float4 o;
        o.x = fminf(fmaxf(__fsub_rn(ncx, __fmul_rn(0.5f, nw)), 0.0f), IMGW);
        o.y = fminf(fmaxf(__fsub_rn(ncy, __fmul_rn(0.5f, nh)), 0.0f), IMGH);
        o.z = fminf(fmaxf(__fadd_rn(ncx, __fmul_rn(0.5f, nw)), 0.0f), IMGW);
        o.w = fminf(fmaxf(__fadd_rn(ncy, __fmul_rn(0.5f, nh)), 0.0f), IMGH);
        *reinterpret_cast<float4*>(out_pred + ((size_t)b * NPG + p) * 4) = o;
    }

    // ---- labels + argmax ----
    float label;
    if (!isprop) {
        // appended GT box: self-IoU == 1.0 >= 0.5, and it never feeds the
        // per-GT argmax (which is over the first N proposals only).
        label = 1.0f;
    } else {
        const float area_a = __fmul_rn(__fsub_rn(a.z, a.x), __fsub_rn(a.w, a.y));
        float vmax = 0.0f;
        unsigned long long* keyrow = g_keys + b * GG;
        const unsigned low = 0xFFFFFFFFu - (unsigned)p;

        const int bin = (int)(a.y * BINW_INV) * NBX + (int)(a.x * BINW_INV);
        uint4 m4 = *reinterpret_cast<const uint4*>(&smask[bin * 4]);
        unsigned mw[4] = {m4.x, m4.y, m4.z, m4.w};

#pragma unroll
        for (int w = 0; w < 4; w++) {
            unsigned m = mw[w];
            while (m) {
                int g = (w << 5) + (__ffs(m) - 1);
                m &= m - 1;
                float4 gb = sg[g];
                float ltx = fmaxf(a.x, gb.x);
                float lty = fmaxf(a.y, gb.y);
                float rbx = fminf(a.z, gb.z);
                float rby = fminf(a.w, gb.w);
                float ww = __fsub_rn(rbx, ltx);
                float hh = __fsub_rn(rby, lty);
                if (ww > 0.0f && hh > 0.0f) {
                    float inter = __fmul_rn(ww, hh);
                    float uni   = __fsub_rn(__fadd_rn(sa[g], area_a), inter);
                    float q     = __fdiv_rn(inter, uni);
                    vmax = fmaxf(vmax, q);
                    unsigned long long key =
                        ((unsigned long long)__float_as_uint(q) << 32) | low;
                    atomicMax(keyrow + g, key);
                }
            }
        }
        label = (vmax >= 0.5f) ? 1.0f : 0.0f;
    }
    out_labels[(size_t)b * NPG + p] = label;
}

// ---------------------------------------------------------------------------
// Epilogue: decode argmax keys -> reg targets + roi_scores. atomicExch
// consumes AND resets each key (ready for the next graph replay).
// ---------------------------------------------------------------------------
__global__ __launch_bounds__(256)
void epilogue_kernel(const float* __restrict__ props,
                     const float* __restrict__ gts,
                     float* __restrict__ out_regt,
                     float* __restrict__ out_scores) {
    int i = blockIdx.x * 256 + threadIdx.x;
    if (i >= BB * GG) return;
    int b = i >> 7;
    int g = i & (GG - 1);

    unsigned long long key = atomicExch(&g_keys[i], 0ull);
    float q = __uint_as_float((unsigned)(key >> 32));
    unsigned idx = (key == 0ull) ? 0u
                 : (0xFFFFFFFFu - (unsigned)(key & 0xFFFFFFFFull));

    float4 mp = ld4(props + ((size_t)b * NN + idx) * 4);
    float4 gb = ld4(gts + ((size_t)b * GG + g) * 4);

    float pw  = __fsub_rn(mp.z, mp.x);
    float ph  = __fsub_rn(mp.w, mp.y);
    float pcx = __fadd_rn(mp.x, __fmul_rn(0.5f, pw));
    float pcy = __fadd_rn(mp.y, __fmul_rn(0.5f, ph));
    float gw  = __fsub_rn(gb.z, gb.x);
    float gh  = __fsub_rn(gb.w, gb.y);
    float gcx = __fadd_rn(gb.x, __fmul_rn(0.5f, gw));
    float gcy = __fadd_rn(gb.y, __fmul_rn(0.5f, gh));

    float dx = __fdiv_rn(__fmul_rn(10.0f, __fsub_rn(gcx, pcx)), pw);
    float dy = __fdiv_rn(__fmul_rn(10.0f, __fsub_rn(gcy, pcy)), ph);
    float dw = __fmul_rn(5.0f, logf(__fdiv_rn(gw, pw)));
    float dh = __fmul_rn(5.0f, logf(__fdiv_rn(gh, ph)));

    float* o = out_regt + (size_t)i * 4;
    o[0] = dx; o[1] = dy; o[2] = dw; o[3] = dh;
    out_scores[i] = q;
}

// ---------------------------------------------------------------------------
extern "C" void kernel_launch(void* const* d_in, const int* in_sizes, int n_in,
                              void* d_out, int out_size) {
    const float* props = (const float*)d_in[0];   // (B, N, 4)
    const float* gts   = (const float*)d_in[1];   // (B, G, 4)
    const float* reg   = (const float*)d_in[2];   // (B, N+G, 4)

    float* out        = (float*)d_out;
    float* out_pred   = out;                                  // B*(N+G)*4
    float* out_regt   = out_pred + (size_t)BB * NPG * 4;      // B*G*4
    float* out_scores = out_regt + (size_t)BB * GG * 4;       // B*G
    float* out_labels = out_scores + (size_t)BB * GG;         // B*(N+G)

    dim3 gm(GRID_X, BB);
    main_kernel<<<gm, 256>>>(props, gts, reg, out_pred, out_labels);

    epilogue_kernel<<<(BB * GG + 255) / 256, 256>>>(props, gts,
                                                    out_regt, out_scores);
}